// round 14
// baseline (speedup 1.0000x reference)
#include <cuda_runtime.h>

typedef unsigned long long u64;

#define B_SZ   2048
#define T_LEN  256
#define E_DIM  50
#define H_DIM  50
#define G_DIM  200   // 4H
#define KP     56    // padded data row: 14 float4; floats 50..55 = 0
#define WP     68    // w1ts row pitch (16B-aligned, bank-staggered)
#define BPC    14    // batches per CTA
#define NT     416   // 13 warps; 400 gate threads
#define GRID   147   // ceil(2048/14)
#define ITEMS  (BPC * 50)   // 700 update/emb items (bl-major)
#define DITEMS (25 * 7)     // 175 dense items: (dq-pair, bl-pair)

// dynamic smem layout (floats)
#define OFF_XSH   0                        // [2][14][56]
#define OFF_HSH   (OFF_XSH + 2*BPC*KP)     // [14][56]
#define OFF_ZP    (OFF_HSH + BPC*KP)       // [4][14][200]
#define OFF_W1    (OFF_ZP + 4*BPC*G_DIM)   // [50][68]
#define OFF_D1    (OFF_W1 + E_DIM*WP)      // [14][56]
#define OFF_D2    (OFF_D1 + BPC*KP)        // [14][56]
#define OFF_W2    (OFF_D2 + BPC*KP)        // [56]
#define OFF_B2    (OFF_W2 + KP)            // [4]
#define SMEM_FLOATS (OFF_B2 + 4)
#define SMEM_BYTES  (SMEM_FLOATS * 4)

__device__ __forceinline__ u64 ffma2(u64 a, u64 b, u64 c) {
    u64 d; asm("fma.rn.f32x2 %0, %1, %2, %3;" : "=l"(d) : "l"(a), "l"(b), "l"(c));
    return d;
}
__device__ __forceinline__ u64 pack2(float lo, float hi) {
    u64 d; asm("mov.b64 %0, {%1, %2};" : "=l"(d) : "f"(lo), "f"(hi)); return d;
}
__device__ __forceinline__ float sum2(u64 v) {
    float lo, hi; asm("mov.b64 {%0, %1}, %2;" : "=f"(lo), "=f"(hi) : "l"(v));
    return lo + hi;
}
__device__ __forceinline__ float tanhapx(float x) {
    float y; asm("tanh.approx.f32 %0, %1;" : "=f"(y) : "f"(x)); return y;
}
__device__ __forceinline__ float sigapx(float x) {
    return fmaf(tanhapx(0.5f * x), 0.5f, 0.5f);
}
__device__ __forceinline__ float gw(const float* W, int k, int c) {
    return (k < 50) ? W[k * G_DIM + c] : 0.f;   // gate weight, pad 0
}

// ---- gate weights: cols c0,c1; k-window [kb, kb+28); 14 u64 per col ----
#define LWA(m) \
    const u64 wa##m = act ? pack2(gw(Wsrc, kb + 2*(m),     c0), \
                                  gw(Wsrc, kb + 2*(m) + 1, c0)) : 0ull; \
    const u64 wb##m = act ? pack2(gw(Wsrc, kb + 2*(m),     c1), \
                                  gw(Wsrc, kb + 2*(m) + 1, c1)) : 0ull;

#define GQ(i, mA, mB) { ulonglong2 qv = sv[i]; \
    aa0 = ffma2(qv.x, wa##mA, aa0); aa1 = ffma2(qv.y, wa##mB, aa1); \
    ab0 = ffma2(qv.x, wb##mA, ab0); ab1 = ffma2(qv.y, wb##mB, ab1); }

#define GATE_BODY \
    GQ(0,0,1) GQ(1,2,3) GQ(2,4,5) GQ(3,6,7) GQ(4,8,9) GQ(5,10,11) GQ(6,12,13)

// ---- update / prefetch item slots (bl-major) ----
#define ITEM_SETUP(r) \
    const int  u##r  = tid + (r) * NT; \
    const bool v##r  = (u##r < ITEMS); \
    const int  bl##r = v##r ? (u##r / 50) : 0; \
    const int  q##r  = v##r ? (u##r % 50) : 0; \
    const bool s##r  = v##r && (b0 + bl##r < B_SZ); \
    const int* ir##r = inp + (size_t)(s##r ? (b0 + bl##r) : 0) * T_LEN; \
    float cst##r = 0.f; float pre##r = 0.f;

#define PRELOAD(r) if (v##r) \
    XROW(0, bl##r)[q##r] = s##r ? emb[(size_t)ir##r[0] * E_DIM + q##r] : 0.f;

#define PFETCH(r) { pre##r = 0.f; \
    if (s##r && t + 1 < T_LEN) pre##r = emb[(size_t)ir##r[t + 1] * E_DIM + q##r]; }

#define UPDATE(r) if (v##r) { \
    const float* z0 = ZROW(0, bl##r); const float* z1 = ZROW(1, bl##r); \
    const float* z2 = ZROW(2, bl##r); const float* z3 = ZROW(3, bl##r); \
    float zi = (z0[q##r      ] + z1[q##r      ]) + (z2[q##r      ] + z3[q##r      ]); \
    float zf = (z0[q##r +  50] + z1[q##r +  50]) + (z2[q##r +  50] + z3[q##r +  50]); \
    float zg = (z0[q##r + 100] + z1[q##r + 100]) + (z2[q##r + 100] + z3[q##r + 100]); \
    float zo = (z0[q##r + 150] + z1[q##r + 150]) + (z2[q##r + 150] + z3[q##r + 150]); \
    float ig = sigapx(zi), fg = sigapx(zf); \
    float gg = tanhapx(zg), og = sigapx(zo); \
    cst##r = fg * cst##r + ig * gg; \
    HROW(bl##r)[q##r] = og * tanhapx(cst##r); \
    XROW(nxt, bl##r)[q##r] = pre##r; }

// ---- dense 2x2 pass: 2 weight rows x 2 batch rows; FULL 14-chunk row ----
#define DPASS2(S0P, S1P, DROWF) if (dv) { \
    const ulonglong2* w0q = (const ulonglong2*)(sm + OFF_W1 + dq0 * WP); \
    const ulonglong2* w1q = (const ulonglong2*)(sm + OFF_W1 + dq1 * WP); \
    const ulonglong2* s0  = (const ulonglong2*)(S0P); \
    const ulonglong2* s1  = (const ulonglong2*)(S1P); \
    u64 a00 = pack2(b1q0, 0.f), a01 = pack2(b1q1, 0.f); \
    u64 a10 = pack2(b1q0, 0.f), a11 = pack2(b1q1, 0.f); \
    _Pragma("unroll") \
    for (int p = 0; p < 14; p++) { \
        ulonglong2 w0 = w0q[p], w1 = w1q[p], x = s0[p], y = s1[p]; \
        a00 = ffma2(x.x, w0.x, a00); a00 = ffma2(x.y, w0.y, a00); \
        a01 = ffma2(x.x, w1.x, a01); a01 = ffma2(x.y, w1.y, a01); \
        a10 = ffma2(y.x, w0.x, a10); a10 = ffma2(y.y, w0.y, a10); \
        a11 = ffma2(y.x, w1.x, a11); a11 = ffma2(y.y, w1.y, a11); \
    } \
    DROWF(dbl0)[dq0] = fmaxf(sum2(a00), 0.f); \
    DROWF(dbl0)[dq1] = fmaxf(sum2(a01), 0.f); \
    DROWF(dbl1)[dq0] = fmaxf(sum2(a10), 0.f); \
    DROWF(dbl1)[dq1] = fmaxf(sum2(a11), 0.f); }

__global__ void __launch_bounds__(NT, 1)
lstm_fused_all(const int* __restrict__ inp, const float* __restrict__ emb,
               const float* __restrict__ Wk, const float* __restrict__ Uk,
               const float* __restrict__ bias,
               const float* __restrict__ W1, const float* __restrict__ b1,
               const float* __restrict__ W2, const float* __restrict__ b2,
               float* __restrict__ out)
{
    extern __shared__ __align__(16) float sm[];
    #define XROW(buf, bl) (sm + OFF_XSH + (buf) * (BPC * KP) + (bl) * KP)
    #define HROW(bl)      (sm + OFF_HSH + (bl) * KP)
    #define ZROW(qr, bl)  (sm + OFF_ZP + (qr) * (BPC * G_DIM) + (bl) * G_DIM)
    #define D1ROW(bl)     (sm + OFF_D1 + (bl) * KP)
    #define D2ROW(bl)     (sm + OFF_D2 + (bl) * KP)

    const int tid = threadIdx.x;
    const int b0  = blockIdx.x * BPC;

    // ---- gate threads: tid < 400; quarter = role*2 + khalf ----
    const bool act  = (tid < 400);
    const int  quarter = act ? (tid / 100) : 0;       // 0..3
    const int  role = quarter >> 1;                    // 0: x@Wk, 1: h@Uk
    const int  kh   = quarter & 1;                     // k-half
    const int  cp   = act ? (tid % 100) : 0;
    const int  c0   = 2 * cp, c1 = 2 * cp + 1;
    const int  kb   = 28 * kh;                         // k-window base (112B)
    const float* Wsrc = role ? Uk : Wk;
    LWA(0) LWA(1) LWA(2) LWA(3) LWA(4) LWA(5) LWA(6)
    LWA(7) LWA(8) LWA(9) LWA(10) LWA(11) LWA(12) LWA(13)
    const float bgA = (act && quarter == 0) ? bias[c0] : 0.f;
    const float bgB = (act && quarter == 0) ? bias[c1] : 0.f;

    // ---- dense item: (dq-pair, bl-pair); 175 threads ----
    const bool dv   = (tid < DITEMS);
    const int  dqp  = dv ? (tid / 7) : 0;
    const int  dbp  = dv ? (tid % 7) : 0;
    const int  dq0  = 2 * dqp, dq1 = 2 * dqp + 1;
    const int  dbl0 = 2 * dbp, dbl1 = 2 * dbp + 1;
    const float b1q0 = dv ? __ldg(b1 + dq0) : 0.f;
    const float b1q1 = dv ? __ldg(b1 + dq1) : 0.f;

    // Zero all shared (pads stay zero forever)
    for (int i = tid; i < SMEM_FLOATS; i += NT) sm[i] = 0.f;
    __syncthreads();
    // Dense weights transposed into shared (pitch WP, pads zero already)
    for (int i = tid; i < E_DIM * H_DIM; i += NT) {
        int j = i / H_DIM, k = i % H_DIM;
        (sm + OFF_W1)[j * WP + k] = W1[k * E_DIM + j];
    }
    for (int i = tid; i < E_DIM; i += NT) (sm + OFF_W2)[i] = W2[i];
    if (tid == 0) (sm + OFF_B2)[0] = b2[0];

    ITEM_SETUP(0) ITEM_SETUP(1)
    __syncthreads();
    PRELOAD(0) PRELOAD(1)
    __syncthreads();

    for (int t = 0; t < T_LEN; t++) {
        const int cur = t & 1, nxt = cur ^ 1;

        // Prefetch embeddings for t+1 (LDG latency hidden behind gate math)
        PFETCH(0) PFETCH(1)

        // ---- gates(t): 2 cols x half-k per thread; half-rows = 7 LDS.128 ----
        if (act) {
            #pragma unroll 1
            for (int bl = 0; bl < BPC; bl++) {
                const ulonglong2* sv = (const ulonglong2*)
                    ((role ? HROW(bl) : XROW(cur, bl)) + kb);
                u64 aa0 = pack2(bgA, 0.f), aa1 = 0ull;
                u64 ab0 = pack2(bgB, 0.f), ab1 = 0ull;
                GATE_BODY
                float2 zz = make_float2(sum2(aa0) + sum2(aa1),
                                        sum2(ab0) + sum2(ab1));
                *(float2*)&ZROW(quarter, bl)[c0] = zz;
            }
        }
        __syncthreads();

        // ---- state update (Keras order i,f,c,o) + commit x(t+1) ----
        UPDATE(0) UPDATE(1)
        __syncthreads();

        // ---- d1 = relu(h @ W1 + b1), 2x2 blocked ----
        DPASS2(HROW(dbl0), HROW(dbl1), D1ROW)
        __syncthreads();

        // ---- d2 = relu(d1 @ W1 + b1) ----
        DPASS2(D1ROW(dbl0), D1ROW(dbl1), D2ROW)
        __syncthreads();

        // ---- out: sigmoid(d2 . W2 + b2); overlaps next step's gate phase ----
        if (tid < BPC && b0 + tid < B_SZ) {
            const ulonglong2* dv2 = (const ulonglong2*)D2ROW(tid);
            const ulonglong2* wv2 = (const ulonglong2*)(sm + OFF_W2);
            u64 a0 = pack2((sm + OFF_B2)[0], 0.f), a1 = 0ull;
            #pragma unroll
            for (int p = 0; p < 14; p++) {
                ulonglong2 x = dv2[p], y = wv2[p];
                a0 = ffma2(x.x, y.x, a0);
                a1 = ffma2(x.y, y.y, a1);
            }
            out[(size_t)(b0 + tid) * T_LEN + t] = sigapx(sum2(a0) + sum2(a1));
        }
    }
}

// ---------------------------------------------------------------------------
extern "C" void kernel_launch(void* const* d_in, const int* in_sizes, int n_in,
                              void* d_out, int out_size)
{
    const int*   inp = (const int*)  d_in[0];
    const float* emb = (const float*)d_in[1];
    const float* Wk  = (const float*)d_in[2];
    const float* Uk  = (const float*)d_in[3];
    const float* b   = (const float*)d_in[4];
    const float* W1  = (const float*)d_in[5];
    const float* b1  = (const float*)d_in[6];
    const float* W2  = (const float*)d_in[7];
    const float* b2  = (const float*)d_in[8];
    float* out = (float*)d_out;

    cudaFuncSetAttribute(lstm_fused_all,
                         cudaFuncAttributeMaxDynamicSharedMemorySize, SMEM_BYTES);
    lstm_fused_all<<<GRID, NT, SMEM_BYTES>>>(inp, emb, Wk, Uk, b,
                                             W1, b1, W2, b2, out);
}

// round 15
// speedup vs baseline: 1.2828x; 1.2828x over previous
#include <cuda_runtime.h>

typedef unsigned long long u64;

#define B_SZ   2048
#define T_LEN  256
#define E_DIM  50
#define H_DIM  50
#define G_DIM  200   // 4H
#define KP     52    // padded row (13 * float4 = 26 f32x2)
#define BPC    14    // batches per CTA
#define NT     416   // 13 warps; 400 gate threads
#define GRID   147   // ceil(2048/14)
#define ITEMS  (BPC * 50)   // 700 update/emb items (bl-major)
#define DITEMS (50 * 7)     // 350 dense items: (dq, dbp); batches dbp & dbp+7

__device__ __forceinline__ u64 ffma2(u64 a, u64 b, u64 c) {
    u64 d; asm("fma.rn.f32x2 %0, %1, %2, %3;" : "=l"(d) : "l"(a), "l"(b), "l"(c));
    return d;
}
__device__ __forceinline__ u64 pack2(float lo, float hi) {
    u64 d; asm("mov.b64 %0, {%1, %2};" : "=l"(d) : "f"(lo), "f"(hi)); return d;
}
__device__ __forceinline__ float sum2(u64 v) {
    float lo, hi; asm("mov.b64 {%0, %1}, %2;" : "=f"(lo), "=f"(hi) : "l"(v));
    return lo + hi;
}
__device__ __forceinline__ float tanhapx(float x) {
    float y; asm("tanh.approx.f32 %0, %1;" : "=f"(y) : "f"(x)); return y;
}
__device__ __forceinline__ float sigapx(float x) {
    return fmaf(tanhapx(0.5f * x), 0.5f, 0.5f);
}

// ---- gate weights: 50 scalars as 25 packed u64 (strided global load) ----
#define LDWP(m) const u64 wp##m = act ? \
    pack2(wb[(2*(m)) * G_DIM], wb[(2*(m)+1) * G_DIM]) : 0ull;

// One ulonglong2 (4 floats) of both rows in a block-pair vs 2 weight pairs
#define GPP(i, m0, m1) { ulonglong2 qa = svA[i], qb = svB[i]; \
    aA0 = ffma2(qa.x, wp##m0, aA0); aA1 = ffma2(qa.y, wp##m1, aA1); \
    aB0 = ffma2(qb.x, wp##m0, aB0); aB1 = ffma2(qb.y, wp##m1, aB1); }

#define GATE_PAIR_BODY \
    GPP(0,0,1)   GPP(1,2,3)   GPP(2,4,5)   GPP(3,6,7)   GPP(4,8,9) \
    GPP(5,10,11) GPP(6,12,13) GPP(7,14,15) GPP(8,16,17) GPP(9,18,19) \
    GPP(10,20,21) GPP(11,22,23) GPP(12,24,25)

// ---- update / prefetch item slots (bl-major: broadcast/coalesced) ----
#define ITEM_SETUP(r) \
    const int  u##r  = tid + (r) * NT; \
    const bool v##r  = (u##r < ITEMS); \
    const int  bl##r = v##r ? (u##r / 50) : 0; \
    const int  q##r  = v##r ? (u##r % 50) : 0; \
    const bool s##r  = v##r && (b0 + bl##r < B_SZ); \
    const int* ir##r = inp + (size_t)(s##r ? (b0 + bl##r) : 0) * T_LEN; \
    float cst##r = 0.f; float pre##r = 0.f;

#define PRELOAD(r) if (v##r) \
    xsh[0][bl##r][q##r] = s##r ? emb[(size_t)ir##r[0] * E_DIM + q##r] : 0.f;

#define PFETCH(r) { pre##r = 0.f; \
    if (s##r && t + 1 < T_LEN) pre##r = emb[(size_t)ir##r[t + 1] * E_DIM + q##r]; }

#define UPDATE(r) if (v##r) { \
    float zi = zpart[0][bl##r][q##r]       + zpart[1][bl##r][q##r]; \
    float zf = zpart[0][bl##r][q##r +  50] + zpart[1][bl##r][q##r +  50]; \
    float zg = zpart[0][bl##r][q##r + 100] + zpart[1][bl##r][q##r + 100]; \
    float zo = zpart[0][bl##r][q##r + 150] + zpart[1][bl##r][q##r + 150]; \
    float ig = sigapx(zi), fg = sigapx(zf); \
    float gg = tanhapx(zg), og = sigapx(zo); \
    cst##r = fg * cst##r + ig * gg; \
    hsh[bl##r][q##r] = og * tanhapx(cst##r); \
    xsh[nxt][bl##r][q##r] = pre##r; }

// ---- dense pass: weight row shared by 7-lane groups; 2 strided batches ----
#define DPASS(SRC0, SRC1, DST0, DST1) if (dv) { \
    const ulonglong2* wq = (const ulonglong2*)w1ts[dq]; \
    const ulonglong2* s0 = (const ulonglong2*)(SRC0); \
    const ulonglong2* s1 = (const ulonglong2*)(SRC1); \
    u64 a0 = pack2(b1q, 0.f), a1 = 0ull; \
    u64 c0 = pack2(b1q, 0.f), c1 = 0ull; \
    _Pragma("unroll") \
    for (int p = 0; p < 13; p++) { \
        ulonglong2 w = wq[p], x = s0[p], y = s1[p]; \
        a0 = ffma2(x.x, w.x, a0); a1 = ffma2(x.y, w.y, a1); \
        c0 = ffma2(y.x, w.x, c0); c1 = ffma2(y.y, w.y, c1); \
    } \
    (DST0) = fmaxf(sum2(a0) + sum2(a1), 0.f); \
    (DST1) = fmaxf(sum2(c0) + sum2(c1), 0.f); }

__global__ void __launch_bounds__(NT, 1)
lstm_fused_all(const int* __restrict__ inp, const float* __restrict__ emb,
               const float* __restrict__ Wk, const float* __restrict__ Uk,
               const float* __restrict__ bias,
               const float* __restrict__ W1, const float* __restrict__ b1,
               const float* __restrict__ W2, const float* __restrict__ b2,
               float* __restrict__ out)
{
    __shared__ __align__(16) float xsh[2][BPC][KP];      // embedded inputs
    __shared__ __align__(16) float hsh[BPC][KP];         // hidden state
    __shared__ __align__(16) float zpart[2][BPC][G_DIM]; // gate partials
    __shared__ __align__(16) float w1ts[E_DIM][KP];      // w1ts[j][k] = W1[k][j]
    __shared__ __align__(16) float d1sh[BPC][KP];
    __shared__ __align__(16) float d2sh[BPC][KP];
    __shared__ __align__(16) float w2s[KP];
    __shared__ float b1s[E_DIM];
    __shared__ float b2sh;

    const int tid = threadIdx.x;
    const int b0  = blockIdx.x * BPC;

    // ---- gate threads: tid < 400; role 0 = x@Wk, role 1 = h@Uk ----
    const bool act  = (tid < 2 * G_DIM);
    const int  role = (tid >= G_DIM) ? 1 : 0;
    const int  g    = act ? (tid % G_DIM) : 0;
    const float* wb = (role ? Uk : Wk) + g;
    LDWP(0)  LDWP(1)  LDWP(2)  LDWP(3)  LDWP(4)  LDWP(5)  LDWP(6)
    LDWP(7)  LDWP(8)  LDWP(9)  LDWP(10) LDWP(11) LDWP(12) LDWP(13)
    LDWP(14) LDWP(15) LDWP(16) LDWP(17) LDWP(18) LDWP(19) LDWP(20)
    LDWP(21) LDWP(22) LDWP(23) LDWP(24)
    const u64 wp25 = 0ull;   // multiplies the zero pad (floats 50,51)
    const float bg = (act && role == 0) ? bias[g] : 0.f;

    // ---- dense item: (dq, dbp); warp = 7-lane weight groups, batches
    //      dbp and dbp+7 (strided pairing -> conflict-free src banks) ----
    const bool dv   = (tid < DITEMS);
    const int  dq   = dv ? (tid / 7) : 0;
    const int  dbp  = dv ? (tid % 7) : 0;
    const int  dbl0 = dbp, dbl1 = dbp + 7;
    const float b1q = dv ? __ldg(b1 + dq) : 0.f;

    // Zero padded shared rows (pads stay zero forever)
    for (int i = tid; i < BPC * KP; i += NT) {
        (&hsh[0][0])[i]    = 0.f;
        (&xsh[0][0][0])[i] = 0.f;
        (&xsh[1][0][0])[i] = 0.f;
        (&d1sh[0][0])[i]   = 0.f;
        (&d2sh[0][0])[i]   = 0.f;
    }
    // Dense weights into shared (transposed, padded)
    for (int i = tid; i < E_DIM * KP; i += NT) {
        int j = i / KP, k = i % KP;
        w1ts[j][k] = (k < H_DIM) ? W1[k * E_DIM + j] : 0.f;
    }
    for (int i = tid; i < KP; i += NT) w2s[i] = (i < E_DIM) ? W2[i] : 0.f;
    if (tid < E_DIM) b1s[tid] = b1[tid];
    if (tid == 0)    b2sh = b2[0];

    ITEM_SETUP(0) ITEM_SETUP(1)
    __syncthreads();
    PRELOAD(0) PRELOAD(1)
    __syncthreads();

    for (int t = 0; t < T_LEN; t++) {
        const int cur = t & 1, nxt = cur ^ 1;

        // Prefetch embeddings for t+1 (LDG latency hidden behind gate math)
        PFETCH(0) PFETCH(1)

        // ---- gates(t): block pairs, f32x2, 4 accumulator chains ----
        if (act) {
            #pragma unroll 1
            for (int blp = 0; blp < BPC; blp += 2) {
                const ulonglong2* svA = (const ulonglong2*)
                    (role ? hsh[blp]     : xsh[cur][blp]);
                const ulonglong2* svB = (const ulonglong2*)
                    (role ? hsh[blp + 1] : xsh[cur][blp + 1]);
                u64 aA0 = pack2(bg, 0.f), aA1 = 0ull;
                u64 aB0 = pack2(bg, 0.f), aB1 = 0ull;
                GATE_PAIR_BODY
                zpart[role][blp][g]     = sum2(aA0) + sum2(aA1);
                zpart[role][blp + 1][g] = sum2(aB0) + sum2(aB1);
            }
        }
        __syncthreads();

        // ---- state update (Keras order i,f,c,o) + commit x(t+1) ----
        UPDATE(0) UPDATE(1)
        __syncthreads();

        // ---- d1 = relu(h @ W1 + b1): broadcast weights, strided batches ----
        DPASS(hsh[dbl0], hsh[dbl1], d1sh[dbl0][dq], d1sh[dbl1][dq])
        __syncthreads();

        // ---- d2 = relu(d1 @ W1 + b1) ----
        DPASS(d1sh[dbl0], d1sh[dbl1], d2sh[dbl0][dq], d2sh[dbl1][dq])
        __syncthreads();

        // ---- out: sigmoid(d2 . W2 + b2); overlaps next step's gate phase ----
        if (tid < BPC && b0 + tid < B_SZ) {
            const ulonglong2* dv2 = (const ulonglong2*)d2sh[tid];
            const ulonglong2* wv2 = (const ulonglong2*)w2s;
            u64 a0 = pack2(b2sh, 0.f), a1 = 0ull;
            #pragma unroll
            for (int p = 0; p < 13; p++) {
                ulonglong2 x = dv2[p], y = wv2[p];
                a0 = ffma2(x.x, y.x, a0);
                a1 = ffma2(x.y, y.y, a1);
            }
            out[(size_t)(b0 + tid) * T_LEN + t] = sigapx(sum2(a0) + sum2(a1));
        }
    }
}

// ---------------------------------------------------------------------------
extern "C" void kernel_launch(void* const* d_in, const int* in_sizes, int n_in,
                              void* d_out, int out_size)
{
    const int*   inp = (const int*)  d_in[0];
    const float* emb = (const float*)d_in[1];
    const float* Wk  = (const float*)d_in[2];
    const float* Uk  = (const float*)d_in[3];
    const float* b   = (const float*)d_in[4];
    const float* W1  = (const float*)d_in[5];
    const float* b1  = (const float*)d_in[6];
    const float* W2  = (const float*)d_in[7];
    const float* b2  = (const float*)d_in[8];
    float* out = (float*)d_out;

    lstm_fused_all<<<GRID, NT>>>(inp, emb, Wk, Uk, b, W1, b1, W2, b2, out);
}

// round 17
// speedup vs baseline: 1.4378x; 1.1209x over previous
#include <cuda_runtime.h>

typedef unsigned long long u64;

#define B_SZ   2048
#define T_LEN  256
#define E_DIM  50
#define H_DIM  50
#define G_DIM  200   // 4H
#define KP     52    // padded row (13 * float4 = 26 f32x2)
#define BPC    14    // batches per CTA
#define NT     416   // 13 warps; 400 gate threads
#define GRID   147   // ceil(2048/14)
#define ITEMS  (BPC * 50)   // 700 update/emb items (bl-major)
#define DITEMS (50 * (BPC / 2))  // 350 dense items: (q, bl-pair)

__device__ __forceinline__ u64 ffma2(u64 a, u64 b, u64 c) {
    u64 d; asm("fma.rn.f32x2 %0, %1, %2, %3;" : "=l"(d) : "l"(a), "l"(b), "l"(c));
    return d;
}
__device__ __forceinline__ u64 pack2(float lo, float hi) {
    u64 d; asm("mov.b64 %0, {%1, %2};" : "=l"(d) : "f"(lo), "f"(hi)); return d;
}
__device__ __forceinline__ float sum2(u64 v) {
    float lo, hi; asm("mov.b64 {%0, %1}, %2;" : "=f"(lo), "=f"(hi) : "l"(v));
    return lo + hi;
}
__device__ __forceinline__ float tanhapx(float x) {
    float y; asm("tanh.approx.f32 %0, %1;" : "=f"(y) : "f"(x)); return y;
}
__device__ __forceinline__ float sigapx(float x) {
    return fmaf(tanhapx(0.5f * x), 0.5f, 0.5f);
}

// ---- gate weights: 50 scalars as 25 packed u64 (strided global load) ----
#define LDWP(m) const u64 wp##m = act ? \
    pack2(wb[(2*(m)) * G_DIM], wb[(2*(m)+1) * G_DIM]) : 0ull;

// One ulonglong2 (4 floats) of both rows in a block-pair vs 2 weight pairs
#define GPP(i, m0, m1) { ulonglong2 qa = svA[i], qb = svB[i]; \
    aA0 = ffma2(qa.x, wp##m0, aA0); aA1 = ffma2(qa.y, wp##m1, aA1); \
    aB0 = ffma2(qb.x, wp##m0, aB0); aB1 = ffma2(qb.y, wp##m1, aB1); }

#define GATE_PAIR_BODY \
    GPP(0,0,1)   GPP(1,2,3)   GPP(2,4,5)   GPP(3,6,7)   GPP(4,8,9) \
    GPP(5,10,11) GPP(6,12,13) GPP(7,14,15) GPP(8,16,17) GPP(9,18,19) \
    GPP(10,20,21) GPP(11,22,23) GPP(12,24,25)

// ---- update / prefetch item slots (bl-major: broadcast/coalesced) ----
#define ITEM_SETUP(r) \
    const int  u##r  = tid + (r) * NT; \
    const bool v##r  = (u##r < ITEMS); \
    const int  bl##r = v##r ? (u##r / 50) : 0; \
    const int  q##r  = v##r ? (u##r % 50) : 0; \
    const bool s##r  = v##r && (b0 + bl##r < B_SZ); \
    const int* ir##r = inp + (size_t)(s##r ? (b0 + bl##r) : 0) * T_LEN; \
    float cst##r = 0.f; float pre##r = 0.f;

#define PRELOAD(r) if (v##r) \
    xsh[0][bl##r][q##r] = s##r ? emb[(size_t)ir##r[0] * E_DIM + q##r] : 0.f;

#define PFETCH(r) { pre##r = 0.f; \
    if (s##r && t + 1 < T_LEN) pre##r = emb[(size_t)ir##r[t + 1] * E_DIM + q##r]; }

#define UPDATE(r) if (v##r) { \
    float zi = zpart[0][bl##r][q##r]       + zpart[1][bl##r][q##r]; \
    float zf = zpart[0][bl##r][q##r +  50] + zpart[1][bl##r][q##r +  50]; \
    float zg = zpart[0][bl##r][q##r + 100] + zpart[1][bl##r][q##r + 100]; \
    float zo = zpart[0][bl##r][q##r + 150] + zpart[1][bl##r][q##r + 150]; \
    float ig = sigapx(zi), fg = sigapx(zf); \
    float gg = tanhapx(zg), og = sigapx(zo); \
    cst##r = fg * cst##r + ig * gg; \
    hsh[bl##r][q##r] = og * tanhapx(cst##r); \
    xsh[nxt][bl##r][q##r] = pre##r; }

// ---- dense pass: weight row loaded once, used for 2 batches (R12 map) ----
#define DPASS(SRC0, SRC1, DST0, DST1) if (dv) { \
    const ulonglong2* wq = (const ulonglong2*)w1ts[dq]; \
    const ulonglong2* s0 = (const ulonglong2*)(SRC0); \
    const ulonglong2* s1 = (const ulonglong2*)(SRC1); \
    u64 a0 = pack2(b1q, 0.f), a1 = 0ull; \
    u64 c0 = pack2(b1q, 0.f), c1 = 0ull; \
    _Pragma("unroll") \
    for (int p = 0; p < 13; p++) { \
        ulonglong2 w = wq[p], x = s0[p], y = s1[p]; \
        a0 = ffma2(x.x, w.x, a0); a1 = ffma2(x.y, w.y, a1); \
        c0 = ffma2(y.x, w.x, c0); c1 = ffma2(y.y, w.y, c1); \
    } \
    (DST0) = fmaxf(sum2(a0) + sum2(a1), 0.f); \
    (DST1) = fmaxf(sum2(c0) + sum2(c1), 0.f); }

__global__ void __launch_bounds__(NT, 1)
lstm_fused_all(const int* __restrict__ inp, const float* __restrict__ emb,
               const float* __restrict__ Wk, const float* __restrict__ Uk,
               const float* __restrict__ bias,
               const float* __restrict__ W1, const float* __restrict__ b1,
               const float* __restrict__ W2, const float* __restrict__ b2,
               float* __restrict__ out)
{
    __shared__ __align__(16) float xsh[2][BPC][KP];      // embedded inputs
    __shared__ __align__(16) float hsh[BPC][KP];         // hidden state
    __shared__ __align__(16) float zpart[2][BPC][G_DIM]; // gate partials
    __shared__ __align__(16) float w1ts[E_DIM][KP];      // w1ts[j][k] = W1[k][j]
    __shared__ __align__(16) float d1sh[BPC][KP];
    __shared__ __align__(16) float d2sh[BPC][KP];
    __shared__ __align__(16) float w2s[KP];
    __shared__ float b1s[E_DIM];
    __shared__ float b2sh;

    const int tid = threadIdx.x;
    const int b0  = blockIdx.x * BPC;

    // ---- gate threads: tid < 400; role 0 = x@Wk, role 1 = h@Uk ----
    const bool act  = (tid < 2 * G_DIM);
    const int  role = (tid >= G_DIM) ? 1 : 0;
    const int  g    = act ? (tid % G_DIM) : 0;
    const float* wb = (role ? Uk : Wk) + g;
    LDWP(0)  LDWP(1)  LDWP(2)  LDWP(3)  LDWP(4)  LDWP(5)  LDWP(6)
    LDWP(7)  LDWP(8)  LDWP(9)  LDWP(10) LDWP(11) LDWP(12) LDWP(13)
    LDWP(14) LDWP(15) LDWP(16) LDWP(17) LDWP(18) LDWP(19) LDWP(20)
    LDWP(21) LDWP(22) LDWP(23) LDWP(24)
    const u64 wp25 = 0ull;   // multiplies the zero pad (floats 50,51)
    const float bg = (act && role == 0) ? bias[g] : 0.f;

    // ---- dense item: (dq, bl-pair) — R12's proven mapping ----
    const bool dv   = (tid < DITEMS);
    const int  dq   = dv ? (tid % 50) : 0;
    const int  dbp  = dv ? (tid / 50) : 0;
    const int  dbl0 = 2 * dbp, dbl1 = 2 * dbp + 1;
    const float b1q = dv ? __ldg(b1 + dq) : 0.f;

    // Zero padded shared rows (pads stay zero forever)
    for (int i = tid; i < BPC * KP; i += NT) {
        (&hsh[0][0])[i]    = 0.f;
        (&xsh[0][0][0])[i] = 0.f;
        (&xsh[1][0][0])[i] = 0.f;
        (&d1sh[0][0])[i]   = 0.f;
        (&d2sh[0][0])[i]   = 0.f;
    }
    // Dense weights into shared (transposed, padded)
    for (int i = tid; i < E_DIM * KP; i += NT) {
        int j = i / KP, k = i % KP;
        w1ts[j][k] = (k < H_DIM) ? W1[k * E_DIM + j] : 0.f;
    }
    for (int i = tid; i < KP; i += NT) w2s[i] = (i < E_DIM) ? W2[i] : 0.f;
    if (tid < E_DIM) b1s[tid] = b1[tid];
    if (tid == 0)    b2sh = b2[0];

    ITEM_SETUP(0) ITEM_SETUP(1)
    __syncthreads();
    PRELOAD(0) PRELOAD(1)
    __syncthreads();

    for (int t = 0; t < T_LEN; t++) {
        const int cur = t & 1, nxt = cur ^ 1;

        // Prefetch embeddings for t+1 (LDG latency hidden behind gate math)
        PFETCH(0) PFETCH(1)

        // ---- gates(t): block pairs, f32x2; unroll 2 pairs => 8 chains ----
        if (act) {
            #pragma unroll 2
            for (int blp = 0; blp < BPC; blp += 2) {
                const ulonglong2* svA = (const ulonglong2*)
                    (role ? hsh[blp]     : xsh[cur][blp]);
                const ulonglong2* svB = (const ulonglong2*)
                    (role ? hsh[blp + 1] : xsh[cur][blp + 1]);
                u64 aA0 = pack2(bg, 0.f), aA1 = 0ull;
                u64 aB0 = pack2(bg, 0.f), aB1 = 0ull;
                GATE_PAIR_BODY
                zpart[role][blp][g]     = sum2(aA0) + sum2(aA1);
                zpart[role][blp + 1][g] = sum2(aB0) + sum2(aB1);
            }
        }
        __syncthreads();

        // ---- state update (Keras order i,f,c,o) + commit x(t+1) ----
        UPDATE(0) UPDATE(1)
        __syncthreads();

        // ---- d1 = relu(h @ W1 + b1): weight chunk reused for 2 batches ----
        DPASS(hsh[dbl0], hsh[dbl1], d1sh[dbl0][dq], d1sh[dbl1][dq])
        __syncthreads();

        // ---- d2 = relu(d1 @ W1 + b1) ----
        DPASS(d1sh[dbl0], d1sh[dbl1], d2sh[dbl0][dq], d2sh[dbl1][dq])
        __syncthreads();

        // ---- out: sigmoid(d2 . W2 + b2); overlaps next step's gate phase ----
        if (tid < BPC && b0 + tid < B_SZ) {
            const ulonglong2* dv2 = (const ulonglong2*)d2sh[tid];
            const ulonglong2* wv2 = (const ulonglong2*)w2s;
            u64 a0 = pack2(b2sh, 0.f), a1 = 0ull;
            #pragma unroll
            for (int p = 0; p < 13; p++) {
                ulonglong2 x = dv2[p], y = wv2[p];
                a0 = ffma2(x.x, y.x, a0);
                a1 = ffma2(x.y, y.y, a1);
            }
            out[(size_t)(b0 + tid) * T_LEN + t] = sigapx(sum2(a0) + sum2(a1));
        }
    }
}

// ---------------------------------------------------------------------------
extern "C" void kernel_launch(void* const* d_in, const int* in_sizes, int n_in,
                              void* d_out, int out_size)
{
    const int*   inp = (const int*)  d_in[0];
    const float* emb = (const float*)d_in[1];
    const float* Wk  = (const float*)d_in[2];
    const float* Uk  = (const float*)d_in[3];
    const float* b   = (const float*)d_in[4];
    const float* W1  = (const float*)d_in[5];
    const float* b1  = (const float*)d_in[6];
    const float* W2  = (const float*)d_in[7];
    const float* b2  = (const float*)d_in[8];
    float* out = (float*)d_out;

    lstm_fused_all<<<GRID, NT>>>(inp, emb, Wk, Uk, b, W1, b1, W2, b2, out);
}